// round 11
// baseline (speedup 1.0000x reference)
#include <cuda_runtime.h>
#include <cuda_fp16.h>
#include <stdint.h>
#include <math.h>

#define F_IN 128
#define HID  16
#define NC   10
#define CP   12            // logical layer-2 channels (padded)
#define CS   16            // agg2/base2 row stride in floats (64B-aligned rows)
#define N_MAX 100000
#define E_MAX 1600000

// ---------------- scratch (allocation-free, aligned) ----------------
// interleaved fp16 tables: per node 64B block; half[2j]=a0[j], half[2j+1]=ad[j]
__device__ __align__(16) __half g_aqh[N_MAX * 32];
// per node: pairs (b0[c], bd[c]) c=0..11 in halves 0..23, rest pad (48B used)
__device__ __align__(16) __half g_bqh[N_MAX * 32];
__device__ __align__(16) float g_base1[N_MAX * HID];  // x @ root1 + b1
__device__ __align__(16) float g_agg1 [N_MAX * HID];  // 64B rows
__device__ __align__(16) float g_deg  [N_MAX];
__device__ __align__(16) float g_base2[N_MAX * CS];   // h @ root2 + b2 (64B rows)
__device__ __align__(16) float g_agg2 [N_MAX * CS];   // 64B rows -> 1-line REDs

static __device__ __forceinline__ unsigned int pack_h2(float a, float b) {
    __half2 h = __floats2half2_rn(a, b);
    return *reinterpret_cast<unsigned int*>(&h);
}

// ---------------- layer-1 node transform (+ zero accumulators) ---------------
__global__ __launch_bounds__(128)
void node1_kernel(const float* __restrict__ x,
                  const float* __restrict__ W1,
                  const float* __restrict__ root1,
                  const float* __restrict__ b1, int N)
{
    __shared__ float sW0[F_IN * HID];
    __shared__ float sWd[F_IN * HID];
    __shared__ float sR [F_IN * HID];
    for (int i = threadIdx.x; i < F_IN * HID; i += blockDim.x) {
        float w0 = W1[i];
        sW0[i] = w0;
        sWd[i] = W1[F_IN * HID + i] - w0;
        sR [i] = root1[i];
    }
    __syncthreads();

    int n = blockIdx.x * blockDim.x + threadIdx.x;
    if (n >= N) return;

    // zero this node's accumulators (runs before edge passes in-stream)
    float4 z4 = make_float4(0.f, 0.f, 0.f, 0.f);
#pragma unroll
    for (int j4 = 0; j4 < HID / 4; j4++)
        *reinterpret_cast<float4*>(&g_agg1[(size_t)n * HID + j4 * 4]) = z4;
#pragma unroll
    for (int c4 = 0; c4 < CP / 4; c4++)        // only channels 0..11 are RED targets
        *reinterpret_cast<float4*>(&g_agg2[(size_t)n * CS + c4 * 4]) = z4;
    g_deg[n] = 0.f;

    float acc0[HID], accd[HID], accr[HID];
#pragma unroll
    for (int j = 0; j < HID; j++) { acc0[j] = 0.f; accd[j] = 0.f; accr[j] = 0.f; }

    const float4* xr = reinterpret_cast<const float4*>(x + (size_t)n * F_IN);
#pragma unroll 4
    for (int k4 = 0; k4 < F_IN / 4; k4++) {
        float4 xv = __ldg(&xr[k4]);
        float xs[4] = { xv.x, xv.y, xv.z, xv.w };
#pragma unroll
        for (int kk = 0; kk < 4; kk++) {
            float xk  = xs[kk];
            int  base = (k4 * 4 + kk) * HID;
#pragma unroll
            for (int j4 = 0; j4 < HID / 4; j4++) {
                float4 w0 = *reinterpret_cast<const float4*>(&sW0[base + j4 * 4]);
                float4 wd = *reinterpret_cast<const float4*>(&sWd[base + j4 * 4]);
                float4 wr = *reinterpret_cast<const float4*>(&sR [base + j4 * 4]);
                acc0[j4*4+0] += xk * w0.x; acc0[j4*4+1] += xk * w0.y;
                acc0[j4*4+2] += xk * w0.z; acc0[j4*4+3] += xk * w0.w;
                accd[j4*4+0] += xk * wd.x; accd[j4*4+1] += xk * wd.y;
                accd[j4*4+2] += xk * wd.z; accd[j4*4+3] += xk * wd.w;
                accr[j4*4+0] += xk * wr.x; accr[j4*4+1] += xk * wr.y;
                accr[j4*4+2] += xk * wr.z; accr[j4*4+3] += xk * wr.w;
            }
        }
    }
    // interleaved pack: half[2j]=a0[j], half[2j+1]=ad[j]  (lane r gathers uint4 @ r*8)
    uint4 u0, u1, u2, u3;
    u0.x = pack_h2(acc0[0],  accd[0]);  u0.y = pack_h2(acc0[1],  accd[1]);
    u0.z = pack_h2(acc0[2],  accd[2]);  u0.w = pack_h2(acc0[3],  accd[3]);
    u1.x = pack_h2(acc0[4],  accd[4]);  u1.y = pack_h2(acc0[5],  accd[5]);
    u1.z = pack_h2(acc0[6],  accd[6]);  u1.w = pack_h2(acc0[7],  accd[7]);
    u2.x = pack_h2(acc0[8],  accd[8]);  u2.y = pack_h2(acc0[9],  accd[9]);
    u2.z = pack_h2(acc0[10], accd[10]); u2.w = pack_h2(acc0[11], accd[11]);
    u3.x = pack_h2(acc0[12], accd[12]); u3.y = pack_h2(acc0[13], accd[13]);
    u3.z = pack_h2(acc0[14], accd[14]); u3.w = pack_h2(acc0[15], accd[15]);
    uint4* dst = reinterpret_cast<uint4*>(&g_aqh[(size_t)n * 32]);
    dst[0] = u0; dst[1] = u1; dst[2] = u2; dst[3] = u3;

#pragma unroll
    for (int j4 = 0; j4 < HID / 4; j4++) {
        *reinterpret_cast<float4*>(&g_base1[(size_t)n * HID + j4 * 4]) =
            make_float4(accr[j4*4]   + b1[j4*4],   accr[j4*4+1] + b1[j4*4+1],
                        accr[j4*4+2] + b1[j4*4+2], accr[j4*4+3] + b1[j4*4+3]);
    }
}

// ---------------- layer-1 edge pass: 4 lanes/edge, ONE 16B gather per lane ---
__global__ void edge1_kernel(const int* __restrict__ ei,
                             const float* __restrict__ attr, int E)
{
    int t = blockIdx.x * blockDim.x + threadIdx.x;
    int e = t >> 2;
    int r = t & 3;
    if (e >= E) return;
    int   s = __ldg(&ei[e]);
    int   d = __ldg(&ei[E + e]);
    float w = __ldg(&attr[e]);

    uint4 g = __ldg(reinterpret_cast<const uint4*>(&g_aqh[(size_t)s * 32 + r * 8]));
    float2 p0 = __half22float2(*reinterpret_cast<__half2*>(&g.x));
    float2 p1 = __half22float2(*reinterpret_cast<__half2*>(&g.y));
    float2 p2 = __half22float2(*reinterpret_cast<__half2*>(&g.z));
    float2 p3 = __half22float2(*reinterpret_cast<__half2*>(&g.w));

    float4 msg = make_float4(fmaf(w, p0.y, p0.x), fmaf(w, p1.y, p1.x),
                             fmaf(w, p2.y, p2.x), fmaf(w, p3.y, p3.x));
    float* dstp = &g_agg1[(size_t)d * HID + r * 4];
    asm volatile("red.global.add.v4.f32 [%0], {%1,%2,%3,%4};"
                 :: "l"(dstp), "f"(msg.x), "f"(msg.y), "f"(msg.z), "f"(msg.w)
                 : "memory");
    if (r == 0) atomicAdd(&g_deg[d], 1.0f);
}

// ---------------- layer-1 finalize + ELU + layer-2 node transform ------------
__global__ __launch_bounds__(128)
void node2_kernel(const float* __restrict__ W2,
                  const float* __restrict__ root2,
                  const float* __restrict__ b2, int N)
{
    __shared__ float sB0[HID * CP];
    __shared__ float sBd[HID * CP];
    __shared__ float sR [HID * CP];
    __shared__ float sb2[CP];
    for (int i = threadIdx.x; i < HID * CP; i += blockDim.x) {
        int j = i / CP, c = i - j * CP;
        float w0 = (c < NC) ? W2[j * NC + c] : 0.f;
        float w1 = (c < NC) ? W2[HID * NC + j * NC + c] : 0.f;
        sB0[i] = w0;
        sBd[i] = w1 - w0;
        sR [i] = (c < NC) ? root2[j * NC + c] : 0.f;
    }
    if (threadIdx.x < CP) sb2[threadIdx.x] = (threadIdx.x < NC) ? b2[threadIdx.x] : 0.f;
    __syncthreads();

    int n = blockIdx.x * blockDim.x + threadIdx.x;
    if (n >= N) return;

    float inv = 1.f / fmaxf(g_deg[n], 1.f);
    float h[HID];
#pragma unroll
    for (int j4 = 0; j4 < HID / 4; j4++) {
        float4 ag = *reinterpret_cast<const float4*>(&g_agg1 [(size_t)n * HID + j4 * 4]);
        float4 bs = *reinterpret_cast<const float4*>(&g_base1[(size_t)n * HID + j4 * 4]);
        float v[4] = { ag.x * inv + bs.x, ag.y * inv + bs.y,
                       ag.z * inv + bs.z, ag.w * inv + bs.w };
#pragma unroll
        for (int q = 0; q < 4; q++)
            h[j4 * 4 + q] = (v[q] > 0.f) ? v[q] : expm1f(v[q]);
    }

    float o0[CP], od[CP], orr[CP];
#pragma unroll
    for (int c = 0; c < CP; c++) { o0[c] = 0.f; od[c] = 0.f; orr[c] = 0.f; }
#pragma unroll
    for (int j = 0; j < HID; j++) {
        float hj = h[j];
#pragma unroll
        for (int c4 = 0; c4 < CP / 4; c4++) {
            float4 w0 = *reinterpret_cast<const float4*>(&sB0[j * CP + c4 * 4]);
            float4 wd = *reinterpret_cast<const float4*>(&sBd[j * CP + c4 * 4]);
            float4 wr = *reinterpret_cast<const float4*>(&sR [j * CP + c4 * 4]);
            o0[c4*4+0] += hj * w0.x; o0[c4*4+1] += hj * w0.y;
            o0[c4*4+2] += hj * w0.z; o0[c4*4+3] += hj * w0.w;
            od[c4*4+0] += hj * wd.x; od[c4*4+1] += hj * wd.y;
            od[c4*4+2] += hj * wd.z; od[c4*4+3] += hj * wd.w;
            orr[c4*4+0] += hj * wr.x; orr[c4*4+1] += hj * wr.y;
            orr[c4*4+2] += hj * wr.z; orr[c4*4+3] += hj * wr.w;
        }
    }
    // interleaved pack: half[2c]=b0[c], half[2c+1]=bd[c], c=0..11
    uint4 u0, u1, u2;
    u0.x = pack_h2(o0[0],  od[0]);  u0.y = pack_h2(o0[1],  od[1]);
    u0.z = pack_h2(o0[2],  od[2]);  u0.w = pack_h2(o0[3],  od[3]);
    u1.x = pack_h2(o0[4],  od[4]);  u1.y = pack_h2(o0[5],  od[5]);
    u1.z = pack_h2(o0[6],  od[6]);  u1.w = pack_h2(o0[7],  od[7]);
    u2.x = pack_h2(o0[8],  od[8]);  u2.y = pack_h2(o0[9],  od[9]);
    u2.z = pack_h2(o0[10], od[10]); u2.w = pack_h2(o0[11], od[11]);
    uint4* dst = reinterpret_cast<uint4*>(&g_bqh[(size_t)n * 32]);
    dst[0] = u0; dst[1] = u1; dst[2] = u2;

#pragma unroll
    for (int c4 = 0; c4 < CP / 4; c4++) {
        *reinterpret_cast<float4*>(&g_base2[(size_t)n * CS + c4 * 4]) =
            make_float4(orr[c4*4]   + sb2[c4*4],   orr[c4*4+1] + sb2[c4*4+1],
                        orr[c4*4+2] + sb2[c4*4+2], orr[c4*4+3] + sb2[c4*4+3]);
    }
}

// ---------------- layer-2 edge pass: 3 lanes/edge, ONE 16B gather per lane ---
// agg2 rows are 64B-aligned (CS=16): each edge's three red.v4 hit ONE 128B line
__global__ void edge2_kernel(const int* __restrict__ ei,
                             const float* __restrict__ attr, int E)
{
    int t    = blockIdx.x * blockDim.x + threadIdx.x;
    int warp = t >> 5;
    int lane = t & 31;
    if (lane >= 30) return;
    int el = lane / 3;                // 0..9
    int r  = lane - el * 3;           // 0..2
    int e  = warp * 10 + el;
    if (e >= E) return;

    int   s = __ldg(&ei[e]);
    int   d = __ldg(&ei[E + e]);
    float w = __ldg(&attr[e]);

    uint4 g = __ldg(reinterpret_cast<const uint4*>(&g_bqh[(size_t)s * 32 + r * 8]));
    float2 p0 = __half22float2(*reinterpret_cast<__half2*>(&g.x));
    float2 p1 = __half22float2(*reinterpret_cast<__half2*>(&g.y));
    float2 p2 = __half22float2(*reinterpret_cast<__half2*>(&g.z));
    float2 p3 = __half22float2(*reinterpret_cast<__half2*>(&g.w));

    float4 msg = make_float4(fmaf(w, p0.y, p0.x), fmaf(w, p1.y, p1.x),
                             fmaf(w, p2.y, p2.x), fmaf(w, p3.y, p3.x));
    float* dstp = &g_agg2[(size_t)d * CS + r * 4];
    asm volatile("red.global.add.v4.f32 [%0], {%1,%2,%3,%4};"
                 :: "l"(dstp), "f"(msg.x), "f"(msg.y), "f"(msg.z), "f"(msg.w)
                 : "memory");
}

// ---------------- output: 4 lanes/node (r<3 active), v4 loads ----------------
__global__ void out_kernel(float* __restrict__ out, int N)
{
    int t = blockIdx.x * blockDim.x + threadIdx.x;
    int n = t >> 2;
    int r = t & 3;
    if (n >= N || r == 3) return;

    float inv = 1.f / fmaxf(g_deg[n], 1.f);
    float4 ag = *reinterpret_cast<const float4*>(&g_agg2 [(size_t)n * CS + r * 4]);
    float4 bs = *reinterpret_cast<const float4*>(&g_base2[(size_t)n * CS + r * 4]);
    float o[4] = { ag.x * inv + bs.x, ag.y * inv + bs.y,
                   ag.z * inv + bs.z, ag.w * inv + bs.w };

    float* op = out + (size_t)n * NC + r * 4;
    int lim = NC - r * 4;                 // 4,4,2 for r=0,1,2
#pragma unroll
    for (int q = 0; q < 4; q++)
        if (q < lim) op[q] = o[q];
}

// ---------------- launcher ----------------
extern "C" void kernel_launch(void* const* d_in, const int* in_sizes, int n_in,
                              void* d_out, int out_size)
{
    const float* x     = (const float*)d_in[0];
    const int*   ei    = (const int*)d_in[1];
    const float* attr  = (const float*)d_in[2];
    const float* W1    = (const float*)d_in[3];
    const float* root1 = (const float*)d_in[4];
    const float* b1    = (const float*)d_in[5];
    const float* W2    = (const float*)d_in[6];
    const float* root2 = (const float*)d_in[7];
    const float* b2    = (const float*)d_in[8];
    float*       out   = (float*)d_out;

    int N = in_sizes[0] / F_IN;
    int E = in_sizes[2];

    node1_kernel<<<(N + 127) / 128, 128>>>(x, W1, root1, b1, N);

    long long t1 = (long long)E * 4;
    edge1_kernel<<<(unsigned)((t1 + 255) / 256), 256>>>(ei, attr, E);

    node2_kernel<<<(N + 127) / 128, 128>>>(W2, root2, b2, N);

    long long nwarps = ((long long)E + 9) / 10;
    long long t2 = nwarps * 32;
    edge2_kernel<<<(unsigned)((t2 + 255) / 256), 256>>>(ei, attr, E);

    out_kernel<<<(N * 4 + 255) / 256, 256>>>(out, N);
}

// round 12
// speedup vs baseline: 1.0427x; 1.0427x over previous
#include <cuda_runtime.h>
#include <cuda_fp16.h>
#include <stdint.h>
#include <math.h>

#define F_IN 128
#define HID  16
#define NC   10
#define CP   12
#define N_MAX 100000
#define E_MAX 1600000

// ---------------- scratch (allocation-free, aligned) ----------------
// interleaved fp16 tables: per node 64B block; half[2j]=a0[j], half[2j+1]=ad[j]
__device__ __align__(16) __half g_aqh[N_MAX * 32];
// per node: pairs (b0[c], bd[c]) c=0..11 in halves 0..23, rest pad (48B used)
__device__ __align__(16) __half g_bqh[N_MAX * 32];
__device__ __align__(16) float g_base1[N_MAX * HID];  // x @ root1 + b1
__device__ __align__(16) float g_agg1 [N_MAX * HID];
__device__ __align__(16) float g_deg  [N_MAX];
__device__ __align__(16) float g_base2[N_MAX * CP];   // h @ root2 + b2
__device__ __align__(16) float g_agg2 [N_MAX * CP];

static __device__ __forceinline__ unsigned int pack_h2(float a, float b) {
    __half2 h = __floats2half2_rn(a, b);
    return *reinterpret_cast<unsigned int*>(&h);
}

// ---------------- layer-1 node transform (+ zero accumulators) ---------------
__global__ __launch_bounds__(128)
void node1_kernel(const float* __restrict__ x,
                  const float* __restrict__ W1,
                  const float* __restrict__ root1,
                  const float* __restrict__ b1, int N)
{
    __shared__ float sW0[F_IN * HID];
    __shared__ float sWd[F_IN * HID];
    __shared__ float sR [F_IN * HID];
    for (int i = threadIdx.x; i < F_IN * HID; i += blockDim.x) {
        float w0 = W1[i];
        sW0[i] = w0;
        sWd[i] = W1[F_IN * HID + i] - w0;
        sR [i] = root1[i];
    }
    __syncthreads();

    int n = blockIdx.x * blockDim.x + threadIdx.x;
    if (n >= N) return;

    // zero this node's accumulators (runs before edge passes in-stream)
    float4 z4 = make_float4(0.f, 0.f, 0.f, 0.f);
#pragma unroll
    for (int j4 = 0; j4 < HID / 4; j4++)
        *reinterpret_cast<float4*>(&g_agg1[(size_t)n * HID + j4 * 4]) = z4;
#pragma unroll
    for (int c4 = 0; c4 < CP / 4; c4++)
        *reinterpret_cast<float4*>(&g_agg2[(size_t)n * CP + c4 * 4]) = z4;
    g_deg[n] = 0.f;

    float acc0[HID], accd[HID], accr[HID];
#pragma unroll
    for (int j = 0; j < HID; j++) { acc0[j] = 0.f; accd[j] = 0.f; accr[j] = 0.f; }

    const float4* xr = reinterpret_cast<const float4*>(x + (size_t)n * F_IN);
#pragma unroll 4
    for (int k4 = 0; k4 < F_IN / 4; k4++) {
        float4 xv = __ldg(&xr[k4]);
        float xs[4] = { xv.x, xv.y, xv.z, xv.w };
#pragma unroll
        for (int kk = 0; kk < 4; kk++) {
            float xk  = xs[kk];
            int  base = (k4 * 4 + kk) * HID;
#pragma unroll
            for (int j4 = 0; j4 < HID / 4; j4++) {
                float4 w0 = *reinterpret_cast<const float4*>(&sW0[base + j4 * 4]);
                float4 wd = *reinterpret_cast<const float4*>(&sWd[base + j4 * 4]);
                float4 wr = *reinterpret_cast<const float4*>(&sR [base + j4 * 4]);
                acc0[j4*4+0] += xk * w0.x; acc0[j4*4+1] += xk * w0.y;
                acc0[j4*4+2] += xk * w0.z; acc0[j4*4+3] += xk * w0.w;
                accd[j4*4+0] += xk * wd.x; accd[j4*4+1] += xk * wd.y;
                accd[j4*4+2] += xk * wd.z; accd[j4*4+3] += xk * wd.w;
                accr[j4*4+0] += xk * wr.x; accr[j4*4+1] += xk * wr.y;
                accr[j4*4+2] += xk * wr.z; accr[j4*4+3] += xk * wr.w;
            }
        }
    }
    // interleaved pack: half[2j]=a0[j], half[2j+1]=ad[j]  (lane r gathers uint4 @ r*8)
    uint4 u0, u1, u2, u3;
    u0.x = pack_h2(acc0[0],  accd[0]);  u0.y = pack_h2(acc0[1],  accd[1]);
    u0.z = pack_h2(acc0[2],  accd[2]);  u0.w = pack_h2(acc0[3],  accd[3]);
    u1.x = pack_h2(acc0[4],  accd[4]);  u1.y = pack_h2(acc0[5],  accd[5]);
    u1.z = pack_h2(acc0[6],  accd[6]);  u1.w = pack_h2(acc0[7],  accd[7]);
    u2.x = pack_h2(acc0[8],  accd[8]);  u2.y = pack_h2(acc0[9],  accd[9]);
    u2.z = pack_h2(acc0[10], accd[10]); u2.w = pack_h2(acc0[11], accd[11]);
    u3.x = pack_h2(acc0[12], accd[12]); u3.y = pack_h2(acc0[13], accd[13]);
    u3.z = pack_h2(acc0[14], accd[14]); u3.w = pack_h2(acc0[15], accd[15]);
    uint4* dst = reinterpret_cast<uint4*>(&g_aqh[(size_t)n * 32]);
    dst[0] = u0; dst[1] = u1; dst[2] = u2; dst[3] = u3;

#pragma unroll
    for (int j4 = 0; j4 < HID / 4; j4++) {
        *reinterpret_cast<float4*>(&g_base1[(size_t)n * HID + j4 * 4]) =
            make_float4(accr[j4*4]   + b1[j4*4],   accr[j4*4+1] + b1[j4*4+1],
                        accr[j4*4+2] + b1[j4*4+2], accr[j4*4+3] + b1[j4*4+3]);
    }
}

// ---------------- layer-1 edge pass: 4 lanes/edge, 2 edges/thread (MLP=2) ----
__global__ void edge1_kernel(const int* __restrict__ ei,
                             const float* __restrict__ attr, int E, int Eh)
{
    int t   = blockIdx.x * blockDim.x + threadIdx.x;
    int idx = t >> 2;
    int r   = t & 3;
    if (idx >= Eh) return;
    int e0 = idx;
    int e1 = idx + Eh;
    bool has1 = (e1 < E);

    int   s0 = __ldg(&ei[e0]);
    int   d0 = __ldg(&ei[E + e0]);
    float w0 = __ldg(&attr[e0]);
    int   s1 = has1 ? __ldg(&ei[e1])     : 0;
    int   d1 = has1 ? __ldg(&ei[E + e1]) : 0;
    float w1 = has1 ? __ldg(&attr[e1])   : 0.f;

    // two independent gathers in flight
    uint4 ga = __ldg(reinterpret_cast<const uint4*>(&g_aqh[(size_t)s0 * 32 + r * 8]));
    uint4 gb = has1 ? __ldg(reinterpret_cast<const uint4*>(&g_aqh[(size_t)s1 * 32 + r * 8]))
                    : make_uint4(0u, 0u, 0u, 0u);

    {
        float2 p0 = __half22float2(*reinterpret_cast<__half2*>(&ga.x));
        float2 p1 = __half22float2(*reinterpret_cast<__half2*>(&ga.y));
        float2 p2 = __half22float2(*reinterpret_cast<__half2*>(&ga.z));
        float2 p3 = __half22float2(*reinterpret_cast<__half2*>(&ga.w));
        float4 msg = make_float4(fmaf(w0, p0.y, p0.x), fmaf(w0, p1.y, p1.x),
                                 fmaf(w0, p2.y, p2.x), fmaf(w0, p3.y, p3.x));
        float* dstp = &g_agg1[(size_t)d0 * HID + r * 4];
        asm volatile("red.global.add.v4.f32 [%0], {%1,%2,%3,%4};"
                     :: "l"(dstp), "f"(msg.x), "f"(msg.y), "f"(msg.z), "f"(msg.w)
                     : "memory");
        if (r == 0) atomicAdd(&g_deg[d0], 1.0f);
    }
    if (has1) {
        float2 p0 = __half22float2(*reinterpret_cast<__half2*>(&gb.x));
        float2 p1 = __half22float2(*reinterpret_cast<__half2*>(&gb.y));
        float2 p2 = __half22float2(*reinterpret_cast<__half2*>(&gb.z));
        float2 p3 = __half22float2(*reinterpret_cast<__half2*>(&gb.w));
        float4 msg = make_float4(fmaf(w1, p0.y, p0.x), fmaf(w1, p1.y, p1.x),
                                 fmaf(w1, p2.y, p2.x), fmaf(w1, p3.y, p3.x));
        float* dstp = &g_agg1[(size_t)d1 * HID + r * 4];
        asm volatile("red.global.add.v4.f32 [%0], {%1,%2,%3,%4};"
                     :: "l"(dstp), "f"(msg.x), "f"(msg.y), "f"(msg.z), "f"(msg.w)
                     : "memory");
        if (r == 0) atomicAdd(&g_deg[d1], 1.0f);
    }
}

// ---------------- layer-1 finalize + ELU + layer-2 node transform ------------
__global__ __launch_bounds__(128)
void node2_kernel(const float* __restrict__ W2,
                  const float* __restrict__ root2,
                  const float* __restrict__ b2, int N)
{
    __shared__ float sB0[HID * CP];
    __shared__ float sBd[HID * CP];
    __shared__ float sR [HID * CP];
    __shared__ float sb2[CP];
    for (int i = threadIdx.x; i < HID * CP; i += blockDim.x) {
        int j = i / CP, c = i - j * CP;
        float w0 = (c < NC) ? W2[j * NC + c] : 0.f;
        float w1 = (c < NC) ? W2[HID * NC + j * NC + c] : 0.f;
        sB0[i] = w0;
        sBd[i] = w1 - w0;
        sR [i] = (c < NC) ? root2[j * NC + c] : 0.f;
    }
    if (threadIdx.x < CP) sb2[threadIdx.x] = (threadIdx.x < NC) ? b2[threadIdx.x] : 0.f;
    __syncthreads();

    int n = blockIdx.x * blockDim.x + threadIdx.x;
    if (n >= N) return;

    float inv = 1.f / fmaxf(g_deg[n], 1.f);
    float h[HID];
#pragma unroll
    for (int j4 = 0; j4 < HID / 4; j4++) {
        float4 ag = *reinterpret_cast<const float4*>(&g_agg1 [(size_t)n * HID + j4 * 4]);
        float4 bs = *reinterpret_cast<const float4*>(&g_base1[(size_t)n * HID + j4 * 4]);
        float v[4] = { ag.x * inv + bs.x, ag.y * inv + bs.y,
                       ag.z * inv + bs.z, ag.w * inv + bs.w };
#pragma unroll
        for (int q = 0; q < 4; q++)
            h[j4 * 4 + q] = (v[q] > 0.f) ? v[q] : expm1f(v[q]);
    }

    float o0[CP], od[CP], orr[CP];
#pragma unroll
    for (int c = 0; c < CP; c++) { o0[c] = 0.f; od[c] = 0.f; orr[c] = 0.f; }
#pragma unroll
    for (int j = 0; j < HID; j++) {
        float hj = h[j];
#pragma unroll
        for (int c4 = 0; c4 < CP / 4; c4++) {
            float4 w0 = *reinterpret_cast<const float4*>(&sB0[j * CP + c4 * 4]);
            float4 wd = *reinterpret_cast<const float4*>(&sBd[j * CP + c4 * 4]);
            float4 wr = *reinterpret_cast<const float4*>(&sR [j * CP + c4 * 4]);
            o0[c4*4+0] += hj * w0.x; o0[c4*4+1] += hj * w0.y;
            o0[c4*4+2] += hj * w0.z; o0[c4*4+3] += hj * w0.w;
            od[c4*4+0] += hj * wd.x; od[c4*4+1] += hj * wd.y;
            od[c4*4+2] += hj * wd.z; od[c4*4+3] += hj * wd.w;
            orr[c4*4+0] += hj * wr.x; orr[c4*4+1] += hj * wr.y;
            orr[c4*4+2] += hj * wr.z; orr[c4*4+3] += hj * wr.w;
        }
    }
    // interleaved pack: half[2c]=b0[c], half[2c+1]=bd[c], c=0..11
    uint4 u0, u1, u2;
    u0.x = pack_h2(o0[0],  od[0]);  u0.y = pack_h2(o0[1],  od[1]);
    u0.z = pack_h2(o0[2],  od[2]);  u0.w = pack_h2(o0[3],  od[3]);
    u1.x = pack_h2(o0[4],  od[4]);  u1.y = pack_h2(o0[5],  od[5]);
    u1.z = pack_h2(o0[6],  od[6]);  u1.w = pack_h2(o0[7],  od[7]);
    u2.x = pack_h2(o0[8],  od[8]);  u2.y = pack_h2(o0[9],  od[9]);
    u2.z = pack_h2(o0[10], od[10]); u2.w = pack_h2(o0[11], od[11]);
    uint4* dst = reinterpret_cast<uint4*>(&g_bqh[(size_t)n * 32]);
    dst[0] = u0; dst[1] = u1; dst[2] = u2;

#pragma unroll
    for (int c4 = 0; c4 < CP / 4; c4++) {
        *reinterpret_cast<float4*>(&g_base2[(size_t)n * CP + c4 * 4]) =
            make_float4(orr[c4*4]   + sb2[c4*4],   orr[c4*4+1] + sb2[c4*4+1],
                        orr[c4*4+2] + sb2[c4*4+2], orr[c4*4+3] + sb2[c4*4+3]);
    }
}

// ---------------- layer-2 edge pass: 3 lanes/edge, 2 edges/thread (MLP=2) ----
__global__ void edge2_kernel(const int* __restrict__ ei,
                             const float* __restrict__ attr, int E, int Eh)
{
    int t    = blockIdx.x * blockDim.x + threadIdx.x;
    int warp = t >> 5;
    int lane = t & 31;
    if (lane >= 30) return;
    int el = lane / 3;                // 0..9
    int r  = lane - el * 3;           // 0..2
    int e0 = warp * 10 + el;
    if (e0 >= Eh) return;
    int e1 = e0 + Eh;
    bool has1 = (e1 < E);

    int   s0 = __ldg(&ei[e0]);
    int   d0 = __ldg(&ei[E + e0]);
    float w0 = __ldg(&attr[e0]);
    int   s1 = has1 ? __ldg(&ei[e1])     : 0;
    int   d1 = has1 ? __ldg(&ei[E + e1]) : 0;
    float w1 = has1 ? __ldg(&attr[e1])   : 0.f;

    uint4 ga = __ldg(reinterpret_cast<const uint4*>(&g_bqh[(size_t)s0 * 32 + r * 8]));
    uint4 gb = has1 ? __ldg(reinterpret_cast<const uint4*>(&g_bqh[(size_t)s1 * 32 + r * 8]))
                    : make_uint4(0u, 0u, 0u, 0u);

    {
        float2 p0 = __half22float2(*reinterpret_cast<__half2*>(&ga.x));
        float2 p1 = __half22float2(*reinterpret_cast<__half2*>(&ga.y));
        float2 p2 = __half22float2(*reinterpret_cast<__half2*>(&ga.z));
        float2 p3 = __half22float2(*reinterpret_cast<__half2*>(&ga.w));
        float4 msg = make_float4(fmaf(w0, p0.y, p0.x), fmaf(w0, p1.y, p1.x),
                                 fmaf(w0, p2.y, p2.x), fmaf(w0, p3.y, p3.x));
        float* dstp = &g_agg2[(size_t)d0 * CP + r * 4];
        asm volatile("red.global.add.v4.f32 [%0], {%1,%2,%3,%4};"
                     :: "l"(dstp), "f"(msg.x), "f"(msg.y), "f"(msg.z), "f"(msg.w)
                     : "memory");
    }
    if (has1) {
        float2 p0 = __half22float2(*reinterpret_cast<__half2*>(&gb.x));
        float2 p1 = __half22float2(*reinterpret_cast<__half2*>(&gb.y));
        float2 p2 = __half22float2(*reinterpret_cast<__half2*>(&gb.z));
        float2 p3 = __half22float2(*reinterpret_cast<__half2*>(&gb.w));
        float4 msg = make_float4(fmaf(w1, p0.y, p0.x), fmaf(w1, p1.y, p1.x),
                                 fmaf(w1, p2.y, p2.x), fmaf(w1, p3.y, p3.x));
        float* dstp = &g_agg2[(size_t)d1 * CP + r * 4];
        asm volatile("red.global.add.v4.f32 [%0], {%1,%2,%3,%4};"
                     :: "l"(dstp), "f"(msg.x), "f"(msg.y), "f"(msg.z), "f"(msg.w)
                     : "memory");
    }
}

// ---------------- output: 4 lanes/node (r<3 active), v4 loads ----------------
__global__ void out_kernel(float* __restrict__ out, int N)
{
    int t = blockIdx.x * blockDim.x + threadIdx.x;
    int n = t >> 2;
    int r = t & 3;
    if (n >= N || r == 3) return;

    float inv = 1.f / fmaxf(g_deg[n], 1.f);
    float4 ag = *reinterpret_cast<const float4*>(&g_agg2 [(size_t)n * CP + r * 4]);
    float4 bs = *reinterpret_cast<const float4*>(&g_base2[(size_t)n * CP + r * 4]);
    float o[4] = { ag.x * inv + bs.x, ag.y * inv + bs.y,
                   ag.z * inv + bs.z, ag.w * inv + bs.w };

    float* op = out + (size_t)n * NC + r * 4;
    int lim = NC - r * 4;                 // 4,4,2 for r=0,1,2
#pragma unroll
    for (int q = 0; q < 4; q++)
        if (q < lim) op[q] = o[q];
}

// ---------------- launcher ----------------
extern "C" void kernel_launch(void* const* d_in, const int* in_sizes, int n_in,
                              void* d_out, int out_size)
{
    const float* x     = (const float*)d_in[0];
    const int*   ei    = (const int*)d_in[1];
    const float* attr  = (const float*)d_in[2];
    const float* W1    = (const float*)d_in[3];
    const float* root1 = (const float*)d_in[4];
    const float* b1    = (const float*)d_in[5];
    const float* W2    = (const float*)d_in[6];
    const float* root2 = (const float*)d_in[7];
    const float* b2    = (const float*)d_in[8];
    float*       out   = (float*)d_out;

    int N  = in_sizes[0] / F_IN;
    int E  = in_sizes[2];
    int Eh = (E + 1) / 2;

    node1_kernel<<<(N + 127) / 128, 128>>>(x, W1, root1, b1, N);

    long long t1 = (long long)Eh * 4;
    edge1_kernel<<<(unsigned)((t1 + 255) / 256), 256>>>(ei, attr, E, Eh);

    node2_kernel<<<(N + 127) / 128, 128>>>(W2, root2, b2, N);

    long long nwarps = ((long long)Eh + 9) / 10;
    long long t2 = nwarps * 32;
    edge2_kernel<<<(unsigned)((t2 + 255) / 256), 256>>>(ei, attr, E, Eh);

    out_kernel<<<(N * 4 + 255) / 256, 256>>>(out, N);
}

// round 14
// speedup vs baseline: 1.0929x; 1.0482x over previous
#include <cuda_runtime.h>
#include <cuda_fp16.h>
#include <stdint.h>
#include <math.h>

#define F_IN 128
#define HID  16
#define NC   10
#define CP   12
#define N_MAX 100000
#define E_MAX 1600000

// ---------------- scratch (allocation-free, aligned) ----------------
// interleaved fp16 tables: per node 64B block; half[2j]=a0[j], half[2j+1]=ad[j]
__device__ __align__(16) __half g_aqh[N_MAX * 32];
// per node: pairs (b0[c], bd[c]) c=0..11 in halves 0..23, rest pad (48B used)
__device__ __align__(16) __half g_bqh[N_MAX * 32];
__device__ __align__(16) float g_base1[N_MAX * HID];  // x @ root1 + b1
__device__ __align__(16) float g_agg1 [N_MAX * HID];
__device__ __align__(16) float g_deg  [N_MAX];
__device__ __align__(16) float g_base2[N_MAX * CP];   // h @ root2 + b2
__device__ __align__(16) float g_agg2 [N_MAX * CP];

static __device__ __forceinline__ unsigned int pack_h2(float a, float b) {
    __half2 h = __floats2half2_rn(a, b);
    return *reinterpret_cast<unsigned int*>(&h);
}

// ---------------- layer-1 node transform: 2 threads/node ---------------------
// thread r in {0,1} computes output channels j in [r*8, r*8+8) of a0/ad/root
__global__ __launch_bounds__(256)
void node1_kernel(const float* __restrict__ x,
                  const float* __restrict__ W1,
                  const float* __restrict__ root1,
                  const float* __restrict__ b1, int N)
{
    __shared__ float sW0[F_IN * HID];
    __shared__ float sWd[F_IN * HID];
    __shared__ float sR [F_IN * HID];
    for (int i = threadIdx.x; i < F_IN * HID; i += blockDim.x) {
        float w0 = W1[i];
        sW0[i] = w0;
        sWd[i] = W1[F_IN * HID + i] - w0;
        sR [i] = root1[i];
    }
    __syncthreads();

    int t = blockIdx.x * blockDim.x + threadIdx.x;
    int n = t >> 1;
    int r = t & 1;
    if (n >= N) return;

    // zero accumulators, split across the pair
    float4 z4 = make_float4(0.f, 0.f, 0.f, 0.f);
    if (r == 0) {
#pragma unroll
        for (int j4 = 0; j4 < HID / 4; j4++)
            *reinterpret_cast<float4*>(&g_agg1[(size_t)n * HID + j4 * 4]) = z4;
    } else {
#pragma unroll
        for (int c4 = 0; c4 < CP / 4; c4++)
            *reinterpret_cast<float4*>(&g_agg2[(size_t)n * CP + c4 * 4]) = z4;
        g_deg[n] = 0.f;
    }

    float acc0[8], accd[8], accr[8];
#pragma unroll
    for (int j = 0; j < 8; j++) { acc0[j] = 0.f; accd[j] = 0.f; accr[j] = 0.f; }

    const float4* xr = reinterpret_cast<const float4*>(x + (size_t)n * F_IN);
    int joff = r * 8;
#pragma unroll 4
    for (int k4 = 0; k4 < F_IN / 4; k4++) {
        float4 xv = __ldg(&xr[k4]);
        float xs[4] = { xv.x, xv.y, xv.z, xv.w };
#pragma unroll
        for (int kk = 0; kk < 4; kk++) {
            float xk  = xs[kk];
            int  base = (k4 * 4 + kk) * HID + joff;
#pragma unroll
            for (int j4 = 0; j4 < 2; j4++) {
                float4 w0 = *reinterpret_cast<const float4*>(&sW0[base + j4 * 4]);
                float4 wd = *reinterpret_cast<const float4*>(&sWd[base + j4 * 4]);
                float4 wr = *reinterpret_cast<const float4*>(&sR [base + j4 * 4]);
                acc0[j4*4+0] += xk * w0.x; acc0[j4*4+1] += xk * w0.y;
                acc0[j4*4+2] += xk * w0.z; acc0[j4*4+3] += xk * w0.w;
                accd[j4*4+0] += xk * wd.x; accd[j4*4+1] += xk * wd.y;
                accd[j4*4+2] += xk * wd.z; accd[j4*4+3] += xk * wd.w;
                accr[j4*4+0] += xk * wr.x; accr[j4*4+1] += xk * wr.y;
                accr[j4*4+2] += xk * wr.z; accr[j4*4+3] += xk * wr.w;
            }
        }
    }
    // interleaved pack: halves 2j..2j+1 = (a0[j], ad[j]); this thread owns
    // halves [r*16, r*16+16) = two uint4
    uint4 u0, u1;
    u0.x = pack_h2(acc0[0], accd[0]);  u0.y = pack_h2(acc0[1], accd[1]);
    u0.z = pack_h2(acc0[2], accd[2]);  u0.w = pack_h2(acc0[3], accd[3]);
    u1.x = pack_h2(acc0[4], accd[4]);  u1.y = pack_h2(acc0[5], accd[5]);
    u1.z = pack_h2(acc0[6], accd[6]);  u1.w = pack_h2(acc0[7], accd[7]);
    uint4* dst = reinterpret_cast<uint4*>(&g_aqh[(size_t)n * 32 + r * 16]);
    dst[0] = u0; dst[1] = u1;

#pragma unroll
    for (int j4 = 0; j4 < 2; j4++) {
        *reinterpret_cast<float4*>(&g_base1[(size_t)n * HID + joff + j4 * 4]) =
            make_float4(accr[j4*4]   + b1[joff + j4*4],
                        accr[j4*4+1] + b1[joff + j4*4+1],
                        accr[j4*4+2] + b1[joff + j4*4+2],
                        accr[j4*4+3] + b1[joff + j4*4+3]);
    }
}

// ---------------- layer-1 edge pass: 4 lanes/edge, 4 edges/thread (MLP=4) ----
__global__ void edge1_kernel(const int* __restrict__ ei,
                             const float* __restrict__ attr, int E, int Eq)
{
    int t   = blockIdx.x * blockDim.x + threadIdx.x;
    int idx = t >> 2;
    int r   = t & 3;
    if (idx >= Eq) return;

    int   e[4];
    bool  ok[4];
    int   s[4], d[4];
    float w[4];
#pragma unroll
    for (int k = 0; k < 4; k++) {
        e[k]  = idx + k * Eq;
        ok[k] = (e[k] < E);
        s[k]  = ok[k] ? __ldg(&ei[e[k]])     : 0;
        d[k]  = ok[k] ? __ldg(&ei[E + e[k]]) : 0;
        w[k]  = ok[k] ? __ldg(&attr[e[k]])   : 0.f;
    }
    uint4 g[4];
#pragma unroll
    for (int k = 0; k < 4; k++)
        g[k] = ok[k] ? __ldg(reinterpret_cast<const uint4*>(&g_aqh[(size_t)s[k] * 32 + r * 8]))
                     : make_uint4(0u, 0u, 0u, 0u);

#pragma unroll
    for (int k = 0; k < 4; k++) {
        if (!ok[k]) continue;
        float2 p0 = __half22float2(*reinterpret_cast<__half2*>(&g[k].x));
        float2 p1 = __half22float2(*reinterpret_cast<__half2*>(&g[k].y));
        float2 p2 = __half22float2(*reinterpret_cast<__half2*>(&g[k].z));
        float2 p3 = __half22float2(*reinterpret_cast<__half2*>(&g[k].w));
        float4 msg = make_float4(fmaf(w[k], p0.y, p0.x), fmaf(w[k], p1.y, p1.x),
                                 fmaf(w[k], p2.y, p2.x), fmaf(w[k], p3.y, p3.x));
        float* dstp = &g_agg1[(size_t)d[k] * HID + r * 4];
        asm volatile("red.global.add.v4.f32 [%0], {%1,%2,%3,%4};"
                     :: "l"(dstp), "f"(msg.x), "f"(msg.y), "f"(msg.z), "f"(msg.w)
                     : "memory");
        if (r == 0) atomicAdd(&g_deg[d[k]], 1.0f);
    }
}

// ---------------- layer-1 finalize + ELU + layer-2 node transform ------------
__global__ __launch_bounds__(128)
void node2_kernel(const float* __restrict__ W2,
                  const float* __restrict__ root2,
                  const float* __restrict__ b2, int N)
{
    __shared__ float sB0[HID * CP];
    __shared__ float sBd[HID * CP];
    __shared__ float sR [HID * CP];
    __shared__ float sb2[CP];
    for (int i = threadIdx.x; i < HID * CP; i += blockDim.x) {
        int j = i / CP, c = i - j * CP;
        float w0 = (c < NC) ? W2[j * NC + c] : 0.f;
        float w1 = (c < NC) ? W2[HID * NC + j * NC + c] : 0.f;
        sB0[i] = w0;
        sBd[i] = w1 - w0;
        sR [i] = (c < NC) ? root2[j * NC + c] : 0.f;
    }
    if (threadIdx.x < CP) sb2[threadIdx.x] = (threadIdx.x < NC) ? b2[threadIdx.x] : 0.f;
    __syncthreads();

    int n = blockIdx.x * blockDim.x + threadIdx.x;
    if (n >= N) return;

    float inv = 1.f / fmaxf(g_deg[n], 1.f);
    float h[HID];
#pragma unroll
    for (int j4 = 0; j4 < HID / 4; j4++) {
        float4 ag = *reinterpret_cast<const float4*>(&g_agg1 [(size_t)n * HID + j4 * 4]);
        float4 bs = *reinterpret_cast<const float4*>(&g_base1[(size_t)n * HID + j4 * 4]);
        float v[4] = { ag.x * inv + bs.x, ag.y * inv + bs.y,
                       ag.z * inv + bs.z, ag.w * inv + bs.w };
#pragma unroll
        for (int q = 0; q < 4; q++)
            h[j4 * 4 + q] = (v[q] > 0.f) ? v[q] : expm1f(v[q]);
    }

    float o0[CP], od[CP], orr[CP];
#pragma unroll
    for (int c = 0; c < CP; c++) { o0[c] = 0.f; od[c] = 0.f; orr[c] = 0.f; }
#pragma unroll
    for (int j = 0; j < HID; j++) {
        float hj = h[j];
#pragma unroll
        for (int c4 = 0; c4 < CP / 4; c4++) {
            float4 w0 = *reinterpret_cast<const float4*>(&sB0[j * CP + c4 * 4]);
            float4 wd = *reinterpret_cast<const float4*>(&sBd[j * CP + c4 * 4]);
            float4 wr = *reinterpret_cast<const float4*>(&sR [j * CP + c4 * 4]);
            o0[c4*4+0] += hj * w0.x; o0[c4*4+1] += hj * w0.y;
            o0[c4*4+2] += hj * w0.z; o0[c4*4+3] += hj * w0.w;
            od[c4*4+0] += hj * wd.x; od[c4*4+1] += hj * wd.y;
            od[c4*4+2] += hj * wd.z; od[c4*4+3] += hj * wd.w;
            orr[c4*4+0] += hj * wr.x; orr[c4*4+1] += hj * wr.y;
            orr[c4*4+2] += hj * wr.z; orr[c4*4+3] += hj * wr.w;
        }
    }
    // interleaved pack: half[2c]=b0[c], half[2c+1]=bd[c], c=0..11
    uint4 u0, u1, u2;
    u0.x = pack_h2(o0[0],  od[0]);  u0.y = pack_h2(o0[1],  od[1]);
    u0.z = pack_h2(o0[2],  od[2]);  u0.w = pack_h2(o0[3],  od[3]);
    u1.x = pack_h2(o0[4],  od[4]);  u1.y = pack_h2(o0[5],  od[5]);
    u1.z = pack_h2(o0[6],  od[6]);  u1.w = pack_h2(o0[7],  od[7]);
    u2.x = pack_h2(o0[8],  od[8]);  u2.y = pack_h2(o0[9],  od[9]);
    u2.z = pack_h2(o0[10], od[10]); u2.w = pack_h2(o0[11], od[11]);
    uint4* dst = reinterpret_cast<uint4*>(&g_bqh[(size_t)n * 32]);
    dst[0] = u0; dst[1] = u1; dst[2] = u2;

#pragma unroll
    for (int c4 = 0; c4 < CP / 4; c4++) {
        *reinterpret_cast<float4*>(&g_base2[(size_t)n * CP + c4 * 4]) =
            make_float4(orr[c4*4]   + sb2[c4*4],   orr[c4*4+1] + sb2[c4*4+1],
                        orr[c4*4+2] + sb2[c4*4+2], orr[c4*4+3] + sb2[c4*4+3]);
    }
}

// ---------------- layer-2 edge pass: 3 lanes/edge, 4 edges/thread (MLP=4) ----
__global__ void edge2_kernel(const int* __restrict__ ei,
                             const float* __restrict__ attr, int E, int Eq)
{
    int t    = blockIdx.x * blockDim.x + threadIdx.x;
    int warp = t >> 5;
    int lane = t & 31;
    if (lane >= 30) return;
    int el = lane / 3;                // 0..9
    int r  = lane - el * 3;           // 0..2
    int e0 = warp * 10 + el;
    if (e0 >= Eq) return;

    int   e[4];
    bool  ok[4];
    int   s[4], d[4];
    float w[4];
#pragma unroll
    for (int k = 0; k < 4; k++) {
        e[k]  = e0 + k * Eq;
        ok[k] = (e[k] < E);
        s[k]  = ok[k] ? __ldg(&ei[e[k]])     : 0;
        d[k]  = ok[k] ? __ldg(&ei[E + e[k]]) : 0;
        w[k]  = ok[k] ? __ldg(&attr[e[k]])   : 0.f;
    }
    uint4 g[4];
#pragma unroll
    for (int k = 0; k < 4; k++)
        g[k] = ok[k] ? __ldg(reinterpret_cast<const uint4*>(&g_bqh[(size_t)s[k] * 32 + r * 8]))
                     : make_uint4(0u, 0u, 0u, 0u);

#pragma unroll
    for (int k = 0; k < 4; k++) {
        if (!ok[k]) continue;
        float2 p0 = __half22float2(*reinterpret_cast<__half2*>(&g[k].x));
        float2 p1 = __half22float2(*reinterpret_cast<__half2*>(&g[k].y));
        float2 p2 = __half22float2(*reinterpret_cast<__half2*>(&g[k].z));
        float2 p3 = __half22float2(*reinterpret_cast<__half2*>(&g[k].w));
        float4 msg = make_float4(fmaf(w[k], p0.y, p0.x), fmaf(w[k], p1.y, p1.x),
                                 fmaf(w[k], p2.y, p2.x), fmaf(w[k], p3.y, p3.x));
        float* dstp = &g_agg2[(size_t)d[k] * CP + r * 4];
        asm volatile("red.global.add.v4.f32 [%0], {%1,%2,%3,%4};"
                     :: "l"(dstp), "f"(msg.x), "f"(msg.y), "f"(msg.z), "f"(msg.w)
                     : "memory");
    }
}

// ---------------- output: 4 lanes/node (r<3 active), v4 loads ----------------
__global__ void out_kernel(float* __restrict__ out, int N)
{
    int t = blockIdx.x * blockDim.x + threadIdx.x;
    int n = t >> 2;
    int r = t & 3;
    if (n >= N || r == 3) return;

    float inv = 1.f / fmaxf(g_deg[n], 1.f);
    float4 ag = *reinterpret_cast<const float4*>(&g_agg2 [(size_t)n * CP + r * 4]);
    float4 bs = *reinterpret_cast<const float4*>(&g_base2[(size_t)n * CP + r * 4]);
    float o[4] = { ag.x * inv + bs.x, ag.y * inv + bs.y,
                   ag.z * inv + bs.z, ag.w * inv + bs.w };

    float* op = out + (size_t)n * NC + r * 4;
    int lim = NC - r * 4;                 // 4,4,2 for r=0,1,2
#pragma unroll
    for (int q = 0; q < 4; q++)
        if (q < lim) op[q] = o[q];
}

// ---------------- launcher ----------------
extern "C" void kernel_launch(void* const* d_in, const int* in_sizes, int n_in,
                              void* d_out, int out_size)
{
    const float* x     = (const float*)d_in[0];
    const int*   ei    = (const int*)d_in[1];
    const float* attr  = (const float*)d_in[2];
    const float* W1    = (const float*)d_in[3];
    const float* root1 = (const float*)d_in[4];
    const float* b1    = (const float*)d_in[5];
    const float* W2    = (const float*)d_in[6];
    const float* root2 = (const float*)d_in[7];
    const float* b2    = (const float*)d_in[8];
    float*       out   = (float*)d_out;

    int N  = in_sizes[0] / F_IN;
    int E  = in_sizes[2];
    int Eq = (E + 3) / 4;

    node1_kernel<<<(N * 2 + 255) / 256, 256>>>(x, W1, root1, b1, N);

    long long t1 = (long long)Eq * 4;
    edge1_kernel<<<(unsigned)((t1 + 255) / 256), 256>>>(ei, attr, E, Eq);

    node2_kernel<<<(N + 127) / 128, 128>>>(W2, root2, b2, N);

    long long nwarps = ((long long)Eq + 9) / 10;
    long long t2 = nwarps * 32;
    edge2_kernel<<<(unsigned)((t2 + 255) / 256), 256>>>(ei, attr, E, Eq);

    out_kernel<<<(N * 4 + 255) / 256, 256>>>(out, N);
}